// round 6
// baseline (speedup 1.0000x reference)
#include <cuda_runtime.h>

#define BSZ 4
#define NH  16
#define TT  2048
#define DD  1024
#define DH  64

// scratch for q,k,v: [3][B][H][T][64] fp32 (100 MB) — __device__ global, no malloc
static __device__ float g_qkv[(size_t)3 * BSZ * NH * TT * DH];

__device__ __forceinline__ unsigned f2tf(float f) {
    unsigned u;
    asm("cvt.rna.tf32.f32 %0, %1;" : "=r"(u) : "f"(f));
    return u;
}

__device__ __forceinline__ void mma8(float* c,
                                     unsigned a0, unsigned a1, unsigned a2, unsigned a3,
                                     unsigned b0, unsigned b1) {
    asm volatile(
        "mma.sync.aligned.m16n8k8.row.col.f32.tf32.tf32.f32 "
        "{%0,%1,%2,%3},{%4,%5,%6,%7},{%8,%9},{%0,%1,%2,%3};"
        : "+f"(c[0]), "+f"(c[1]), "+f"(c[2]), "+f"(c[3])
        : "r"(a0), "r"(a1), "r"(a2), "r"(a3), "r"(b0), "r"(b1));
}

// ============================================================================
// Kernel 1: QKV projection + q/k normalization.
// grid (T/128, 3*B*H), 256 threads. Block computes Y[t0:t0+128, 0:64] for one
// (n,b,h): Y = X_b^T W_{n,h}, K = 1024 streamed in 32-wide tiles through smem.
// Each warp owns a 16-row m-tile (8 warps * 16 = 128 rows), full 64 cols.
// ============================================================================
__global__ __launch_bounds__(256) void qkv_proj_kernel(const float* __restrict__ x,
                                                       const float* __restrict__ w) {
    __shared__ unsigned sX[32 * 132];  // [d][t] tf32, pad 4
    __shared__ unsigned sW[32 * 68];   // [d][e] tf32, pad 4

    const int t0  = blockIdx.x * 128;
    const int nbh = blockIdx.y;
    const int n   = nbh >> 6;          // 0..2
    const int b   = (nbh >> 4) & 3;
    const int hh  = nbh & 15;

    const float* xb = x + (size_t)b * DD * TT + t0;
    const float* wb = w + (size_t)(n * NH + hh) * DD * DH;

    const int tid  = threadIdx.x;
    const int lane = tid & 31;
    const int wid  = tid >> 5;
    const int grp  = lane >> 2;   // 0..7
    const int tig  = lane & 3;    // 0..3
    const int rb   = wid * 16;    // warp's m-tile base row (within the 128)

    float acc[8][4];
#pragma unroll
    for (int nt = 0; nt < 8; nt++) {
        acc[nt][0] = acc[nt][1] = acc[nt][2] = acc[nt][3] = 0.f;
    }

    for (int kt = 0; kt < DD; kt += 32) {
        // load X tile 32(d) x 128(t): coalesced (t contiguous)
#pragma unroll
        for (int i = 0; i < 16; i++) {
            int idx = i * 256 + tid;
            int dd  = idx >> 7;
            int tt2 = idx & 127;
            sX[dd * 132 + tt2] = f2tf(xb[(size_t)(kt + dd) * TT + tt2]);
        }
        // load W tile 32(d) x 64(e)
#pragma unroll
        for (int i = 0; i < 8; i++) {
            int idx = i * 256 + tid;
            int dd  = idx >> 6;
            int ee  = idx & 63;
            sW[dd * 68 + ee] = f2tf(wb[(kt + dd) * DH + ee]);
        }
        __syncthreads();

#pragma unroll
        for (int ks = 0; ks < 4; ks++) {
            const int k0 = ks * 8;
            // A = X^T: A[t][d] = sX[d][t]
            unsigned a0 = sX[(k0 + tig) * 132 + rb + grp];
            unsigned a1 = sX[(k0 + tig) * 132 + rb + grp + 8];
            unsigned a2 = sX[(k0 + tig + 4) * 132 + rb + grp];
            unsigned a3 = sX[(k0 + tig + 4) * 132 + rb + grp + 8];
#pragma unroll
            for (int nt = 0; nt < 8; nt++) {
                unsigned b0 = sW[(k0 + tig) * 68 + nt * 8 + grp];
                unsigned b1 = sW[(k0 + tig + 4) * 68 + nt * 8 + grp];
                mma8(acc[nt], a0, a1, a2, a3, b0, b1);
            }
        }
        __syncthreads();
    }

    // q,k: normalize each 64-wide row: (y - mean) / (std_unbiased + 1e-5)
    if (n < 2) {
        float slo = 0.f, shi = 0.f;
#pragma unroll
        for (int nt = 0; nt < 8; nt++) {
            slo += acc[nt][0] + acc[nt][1];
            shi += acc[nt][2] + acc[nt][3];
        }
        slo += __shfl_xor_sync(~0u, slo, 1); slo += __shfl_xor_sync(~0u, slo, 2);
        shi += __shfl_xor_sync(~0u, shi, 1); shi += __shfl_xor_sync(~0u, shi, 2);
        float mlo = slo * (1.f / 64.f), mhi = shi * (1.f / 64.f);
        float vlo = 0.f, vhi = 0.f;
#pragma unroll
        for (int nt = 0; nt < 8; nt++) {
            float d0 = acc[nt][0] - mlo, d1 = acc[nt][1] - mlo;
            float d2 = acc[nt][2] - mhi, d3 = acc[nt][3] - mhi;
            vlo += d0 * d0 + d1 * d1;
            vhi += d2 * d2 + d3 * d3;
        }
        vlo += __shfl_xor_sync(~0u, vlo, 1); vlo += __shfl_xor_sync(~0u, vlo, 2);
        vhi += __shfl_xor_sync(~0u, vhi, 1); vhi += __shfl_xor_sync(~0u, vhi, 2);
        float ilo = 1.f / (sqrtf(vlo * (1.f / 63.f)) + 1e-5f);
        float ihi = 1.f / (sqrtf(vhi * (1.f / 63.f)) + 1e-5f);
#pragma unroll
        for (int nt = 0; nt < 8; nt++) {
            acc[nt][0] = (acc[nt][0] - mlo) * ilo;
            acc[nt][1] = (acc[nt][1] - mlo) * ilo;
            acc[nt][2] = (acc[nt][2] - mhi) * ihi;
            acc[nt][3] = (acc[nt][3] - mhi) * ihi;
        }
    }

    float* dst = g_qkv + (((size_t)n * BSZ + b) * NH + hh) * (size_t)TT * DH;
    const int rlo = t0 + rb + grp;
    const int rhi = rlo + 8;
#pragma unroll
    for (int nt = 0; nt < 8; nt++) {
        int e = nt * 8 + 2 * tig;
        *(float2*)(dst + (size_t)rlo * DH + e) = make_float2(acc[nt][0], acc[nt][1]);
        *(float2*)(dst + (size_t)rhi * DH + e) = make_float2(acc[nt][2], acc[nt][3]);
    }
}

// ============================================================================
// Kernel 2: flash attention. grid (T/128, B*H), 256 threads.
// Block owns a 128-query tile for one (b,h); streams 64-wide K/V tiles.
// Per warp: 16 query rows, full 64 output cols. Online softmax in fp32.
// ============================================================================
#define SMEM2_WORDS ((128 + 64 + 64 + 128) * 68)

__global__ __launch_bounds__(256) void attn_kernel(float* __restrict__ out) {
    extern __shared__ unsigned sm[];
    unsigned* sQ = sm;                 // [128][68] tf32
    unsigned* sK = sQ + 128 * 68;      // [64][68]  tf32
    unsigned* sV = sK + 64 * 68;       // [64][68]  tf32
    unsigned* sP = sV + 64 * 68;       // [128][68] tf32

    const int t0 = blockIdx.x * 128;
    const int b  = blockIdx.y >> 4;
    const int hh = blockIdx.y & 15;

    const size_t base = (((size_t)b) * NH + hh) * (size_t)TT * DH;
    const size_t pl   = (size_t)BSZ * NH * TT * DH;
    const float* Qg = g_qkv + base;
    const float* Kg = g_qkv + pl + base;
    const float* Vg = g_qkv + 2 * pl + base;

    const int tid  = threadIdx.x;
    const int lane = tid & 31;
    const int wid  = tid >> 5;
    const int grp  = lane >> 2;
    const int tig  = lane & 3;
    const int rb   = wid * 16;

    // load Q tile once
#pragma unroll
    for (int i = 0; i < 32; i++) {
        int idx = i * 256 + tid;
        int r = idx >> 6, e = idx & 63;
        sQ[r * 68 + e] = f2tf(Qg[(size_t)(t0 + r) * DH + e]);
    }

    float o[8][4];
#pragma unroll
    for (int nt = 0; nt < 8; nt++) { o[nt][0] = o[nt][1] = o[nt][2] = o[nt][3] = 0.f; }
    float mlo = -1e30f, mhi = -1e30f, llo = 0.f, lhi = 0.f;

    for (int s0 = 0; s0 < TT; s0 += 64) {
        // load K,V tiles (64 x 64)
#pragma unroll
        for (int i = 0; i < 16; i++) {
            int idx = i * 256 + tid;
            int r = idx >> 6, e = idx & 63;
            sK[r * 68 + e] = f2tf(Kg[(size_t)(s0 + r) * DH + e]);
            sV[r * 68 + e] = f2tf(Vg[(size_t)(s0 + r) * DH + e]);
        }
        __syncthreads();  // K,V visible (first iter: also covers Q load)

        // S = Q K^T  (16 rows x 64 s-cols per warp)
        float sa[8][4];
#pragma unroll
        for (int nt = 0; nt < 8; nt++) { sa[nt][0] = sa[nt][1] = sa[nt][2] = sa[nt][3] = 0.f; }
#pragma unroll
        for (int ks = 0; ks < 8; ks++) {
            const int k0 = ks * 8;
            unsigned a0 = sQ[(rb + grp) * 68 + k0 + tig];
            unsigned a1 = sQ[(rb + grp + 8) * 68 + k0 + tig];
            unsigned a2 = sQ[(rb + grp) * 68 + k0 + tig + 4];
            unsigned a3 = sQ[(rb + grp + 8) * 68 + k0 + tig + 4];
#pragma unroll
            for (int nt = 0; nt < 8; nt++) {
                unsigned b0 = sK[(nt * 8 + grp) * 68 + k0 + tig];
                unsigned b1 = sK[(nt * 8 + grp) * 68 + k0 + tig + 4];
                mma8(sa[nt], a0, a1, a2, a3, b0, b1);
            }
        }

        // online softmax (scale 1/sqrt(64) = 0.125)
        float txlo = -1e30f, txhi = -1e30f;
#pragma unroll
        for (int nt = 0; nt < 8; nt++) {
            sa[nt][0] *= 0.125f; sa[nt][1] *= 0.125f;
            sa[nt][2] *= 0.125f; sa[nt][3] *= 0.125f;
            txlo = fmaxf(txlo, fmaxf(sa[nt][0], sa[nt][1]));
            txhi = fmaxf(txhi, fmaxf(sa[nt][2], sa[nt][3]));
        }
        txlo = fmaxf(txlo, __shfl_xor_sync(~0u, txlo, 1));
        txlo = fmaxf(txlo, __shfl_xor_sync(~0u, txlo, 2));
        txhi = fmaxf(txhi, __shfl_xor_sync(~0u, txhi, 1));
        txhi = fmaxf(txhi, __shfl_xor_sync(~0u, txhi, 2));
        float nmlo = fmaxf(mlo, txlo), nmhi = fmaxf(mhi, txhi);
        float alo = __expf(mlo - nmlo), ahi = __expf(mhi - nmhi);
        mlo = nmlo; mhi = nmhi;

        float rslo = 0.f, rshi = 0.f;
#pragma unroll
        for (int nt = 0; nt < 8; nt++) {
            sa[nt][0] = __expf(sa[nt][0] - nmlo);
            sa[nt][1] = __expf(sa[nt][1] - nmlo);
            sa[nt][2] = __expf(sa[nt][2] - nmhi);
            sa[nt][3] = __expf(sa[nt][3] - nmhi);
            rslo += sa[nt][0] + sa[nt][1];
            rshi += sa[nt][2] + sa[nt][3];
        }
        rslo += __shfl_xor_sync(~0u, rslo, 1); rslo += __shfl_xor_sync(~0u, rslo, 2);
        rshi += __shfl_xor_sync(~0u, rshi, 1); rshi += __shfl_xor_sync(~0u, rshi, 2);
        llo = llo * alo + rslo;
        lhi = lhi * ahi + rshi;

        // rescale O, stash P (own rows only -> warp-local)
#pragma unroll
        for (int nt = 0; nt < 8; nt++) {
            o[nt][0] *= alo; o[nt][1] *= alo; o[nt][2] *= ahi; o[nt][3] *= ahi;
            int sc = nt * 8 + 2 * tig;
            sP[(rb + grp) * 68 + sc]     = f2tf(sa[nt][0]);
            sP[(rb + grp) * 68 + sc + 1] = f2tf(sa[nt][1]);
            sP[(rb + grp + 8) * 68 + sc]     = f2tf(sa[nt][2]);
            sP[(rb + grp + 8) * 68 + sc + 1] = f2tf(sa[nt][3]);
        }
        __syncwarp();

        // O += P V
#pragma unroll
        for (int ks = 0; ks < 8; ks++) {
            const int k0 = ks * 8;
            unsigned a0 = sP[(rb + grp) * 68 + k0 + tig];
            unsigned a1 = sP[(rb + grp + 8) * 68 + k0 + tig];
            unsigned a2 = sP[(rb + grp) * 68 + k0 + tig + 4];
            unsigned a3 = sP[(rb + grp + 8) * 68 + k0 + tig + 4];
#pragma unroll
            for (int nt = 0; nt < 8; nt++) {
                unsigned b0 = sV[(k0 + tig) * 68 + nt * 8 + grp];
                unsigned b1 = sV[(k0 + tig + 4) * 68 + nt * 8 + grp];
                mma8(o[nt], a0, a1, a2, a3, b0, b1);
            }
        }
        __syncthreads();  // all warps done with sK/sV before next overwrite
    }

    // epilogue: divide by l, write transposed out[b, h*64+e, t]
    float ilo = 1.f / llo, ihi = 1.f / lhi;
    float* ob = out + ((size_t)b * DD + hh * DH) * TT;
    const int rlo = t0 + rb + grp;
    const int rhi = rlo + 8;
#pragma unroll
    for (int nt = 0; nt < 8; nt++) {
        int e = nt * 8 + 2 * tig;
        ob[(size_t)e * TT + rlo]       = o[nt][0] * ilo;
        ob[(size_t)(e + 1) * TT + rlo] = o[nt][1] * ilo;
        ob[(size_t)e * TT + rhi]       = o[nt][2] * ihi;
        ob[(size_t)(e + 1) * TT + rhi] = o[nt][3] * ihi;
    }
}

extern "C" void kernel_launch(void* const* d_in, const int* in_sizes, int n_in,
                              void* d_out, int out_size) {
    (void)in_sizes; (void)n_in; (void)out_size;
    const float* x   = (const float*)d_in[0];   // [4,1024,2048] fp32
    const float* qkv = (const float*)d_in[1];   // [3,16,1024,64] fp32
    float* out = (float*)d_out;                 // [4,1024,2048] fp32

    qkv_proj_kernel<<<dim3(TT / 128, 3 * BSZ * NH), 256>>>(x, qkv);

    const int smem2 = SMEM2_WORDS * 4;  // 104448 B
    cudaFuncSetAttribute(attn_kernel, cudaFuncAttributeMaxDynamicSharedMemorySize, smem2);
    attn_kernel<<<dim3(TT / 128, BSZ * NH), 256, smem2>>>(out);
}

// round 8
// speedup vs baseline: 1.6315x; 1.6315x over previous
#include <cuda_runtime.h>

#define BSZ 4
#define NH  16
#define TT  2048
#define DD  1024
#define DH  64

// scratch for q,k,v: [3][B][H][T][64] fp32 bits (tf32-pre-rounded), 100 MB
static __device__ float g_qkv[(size_t)3 * BSZ * NH * TT * DH];

__device__ __forceinline__ unsigned f2tf(float f) {
    unsigned u;
    asm("cvt.rna.tf32.f32 %0, %1;" : "=r"(u) : "f"(f));
    return u;
}

__device__ __forceinline__ void mma8(float* c,
                                     unsigned a0, unsigned a1, unsigned a2, unsigned a3,
                                     unsigned b0, unsigned b1) {
    asm volatile(
        "mma.sync.aligned.m16n8k8.row.col.f32.tf32.tf32.f32 "
        "{%0,%1,%2,%3},{%4,%5,%6,%7},{%8,%9},{%0,%1,%2,%3};"
        : "+f"(c[0]), "+f"(c[1]), "+f"(c[2]), "+f"(c[3])
        : "r"(a0), "r"(a1), "r"(a2), "r"(a3), "r"(b0), "r"(b1));
}

// ============================================================================
// Kernel 1: QKV projection + q/k normalization.
// grid (T/256, 3*B*H), 256 threads. Block computes Y[t0:t0+256, 0:64] for one
// (n,b,h). Warp owns 32 rows (2 m-tiles) so B fragments are reused 2x.
// float4 global loads, uint4 smem stores. Output stored tf32-pre-rounded.
// ============================================================================
__global__ __launch_bounds__(256, 2) void qkv_proj_kernel(const float* __restrict__ x,
                                                          const float* __restrict__ w) {
    __shared__ unsigned sX[32 * 264];  // [d][t] tf32, pad 8 (16B-aligned rows)
    __shared__ unsigned sW[32 * 72];   // [d][e] tf32, pad 8

    const int t0  = blockIdx.x * 256;
    const int nbh = blockIdx.y;
    const int n   = nbh >> 6;          // 0..2
    const int b   = (nbh >> 4) & 3;
    const int hh  = nbh & 15;

    const float* xb = x + (size_t)b * DD * TT + t0;
    const float* wb = w + (size_t)(n * NH + hh) * DD * DH;

    const int tid  = threadIdx.x;
    const int lane = tid & 31;
    const int wid  = tid >> 5;
    const int grp  = lane >> 2;   // 0..7
    const int tig  = lane & 3;    // 0..3
    const int rb   = wid * 32;    // warp's base row (2 m-tiles)

    float acc[2][8][4];
#pragma unroll
    for (int mt = 0; mt < 2; mt++)
#pragma unroll
        for (int nt = 0; nt < 8; nt++)
            acc[mt][nt][0] = acc[mt][nt][1] = acc[mt][nt][2] = acc[mt][nt][3] = 0.f;

    for (int kt = 0; kt < DD; kt += 32) {
        // X tile 32(d) x 256(t): 8 float4 per thread, coalesced
#pragma unroll
        for (int i = 0; i < 8; i++) {
            int idx = i * 256 + tid;
            int dd  = idx >> 6;       // 0..31
            int t4  = idx & 63;       // 0..63 (float4 col)
            float4 v = *(const float4*)(xb + (size_t)(kt + dd) * TT + t4 * 4);
            uint4 u = make_uint4(f2tf(v.x), f2tf(v.y), f2tf(v.z), f2tf(v.w));
            *(uint4*)&sX[dd * 264 + t4 * 4] = u;
        }
        // W tile 32(d) x 64(e): 2 float4 per thread
#pragma unroll
        for (int i = 0; i < 2; i++) {
            int idx = i * 256 + tid;
            int dd  = idx >> 4;       // 0..31
            int e4  = idx & 15;       // 0..15
            float4 v = *(const float4*)(wb + (size_t)(kt + dd) * DH + e4 * 4);
            uint4 u = make_uint4(f2tf(v.x), f2tf(v.y), f2tf(v.z), f2tf(v.w));
            *(uint4*)&sW[dd * 72 + e4 * 4] = u;
        }
        __syncthreads();

#pragma unroll
        for (int ks = 0; ks < 4; ks++) {
            const int k0 = ks * 8;
            unsigned a[2][4];
#pragma unroll
            for (int mt = 0; mt < 2; mt++) {
                const int r = rb + mt * 16 + grp;
                a[mt][0] = sX[(k0 + tig) * 264 + r];
                a[mt][1] = sX[(k0 + tig) * 264 + r + 8];
                a[mt][2] = sX[(k0 + tig + 4) * 264 + r];
                a[mt][3] = sX[(k0 + tig + 4) * 264 + r + 8];
            }
#pragma unroll
            for (int nt = 0; nt < 8; nt++) {
                unsigned b0 = sW[(k0 + tig) * 72 + nt * 8 + grp];
                unsigned b1 = sW[(k0 + tig + 4) * 72 + nt * 8 + grp];
                mma8(acc[0][nt], a[0][0], a[0][1], a[0][2], a[0][3], b0, b1);
                mma8(acc[1][nt], a[1][0], a[1][1], a[1][2], a[1][3], b0, b1);
            }
        }
        __syncthreads();
    }

    // q,k: normalize each 64-wide row: (y - mean) / (std_unbiased + 1e-5)
    if (n < 2) {
#pragma unroll
        for (int mt = 0; mt < 2; mt++) {
            float slo = 0.f, shi = 0.f;
#pragma unroll
            for (int nt = 0; nt < 8; nt++) {
                slo += acc[mt][nt][0] + acc[mt][nt][1];
                shi += acc[mt][nt][2] + acc[mt][nt][3];
            }
            slo += __shfl_xor_sync(~0u, slo, 1); slo += __shfl_xor_sync(~0u, slo, 2);
            shi += __shfl_xor_sync(~0u, shi, 1); shi += __shfl_xor_sync(~0u, shi, 2);
            float mlo = slo * (1.f / 64.f), mhi = shi * (1.f / 64.f);
            float vlo = 0.f, vhi = 0.f;
#pragma unroll
            for (int nt = 0; nt < 8; nt++) {
                float d0 = acc[mt][nt][0] - mlo, d1 = acc[mt][nt][1] - mlo;
                float d2 = acc[mt][nt][2] - mhi, d3 = acc[mt][nt][3] - mhi;
                vlo += d0 * d0 + d1 * d1;
                vhi += d2 * d2 + d3 * d3;
            }
            vlo += __shfl_xor_sync(~0u, vlo, 1); vlo += __shfl_xor_sync(~0u, vlo, 2);
            vhi += __shfl_xor_sync(~0u, vhi, 1); vhi += __shfl_xor_sync(~0u, vhi, 2);
            float ilo = 1.f / (sqrtf(vlo * (1.f / 63.f)) + 1e-5f);
            float ihi = 1.f / (sqrtf(vhi * (1.f / 63.f)) + 1e-5f);
#pragma unroll
            for (int nt = 0; nt < 8; nt++) {
                acc[mt][nt][0] = (acc[mt][nt][0] - mlo) * ilo;
                acc[mt][nt][1] = (acc[mt][nt][1] - mlo) * ilo;
                acc[mt][nt][2] = (acc[mt][nt][2] - mhi) * ihi;
                acc[mt][nt][3] = (acc[mt][nt][3] - mhi) * ihi;
            }
        }
    }

    // store tf32-pre-rounded bits so attn skips cvt
    float* dst = g_qkv + (((size_t)n * BSZ + b) * NH + hh) * (size_t)TT * DH;
#pragma unroll
    for (int mt = 0; mt < 2; mt++) {
        const int rlo = t0 + rb + mt * 16 + grp;
        const int rhi = rlo + 8;
#pragma unroll
        for (int nt = 0; nt < 8; nt++) {
            int e = nt * 8 + 2 * tig;
            *(float2*)(dst + (size_t)rlo * DH + e) =
                make_float2(__uint_as_float(f2tf(acc[mt][nt][0])),
                            __uint_as_float(f2tf(acc[mt][nt][1])));
            *(float2*)(dst + (size_t)rhi * DH + e) =
                make_float2(__uint_as_float(f2tf(acc[mt][nt][2])),
                            __uint_as_float(f2tf(acc[mt][nt][3])));
        }
    }
}

// ============================================================================
// Kernel 2: flash attention. grid (T/256, B*H), 256 threads.
// Block owns a 256-query tile for one (b,h); warp owns 32 rows (2 m-tiles) so
// K/V fragments are reused 2x. Inputs are tf32-pre-rounded (no cvt on load).
// ============================================================================
#define SMEM2_WORDS ((256 + 64 + 64 + 256) * 68)

__global__ __launch_bounds__(256, 1) void attn_kernel(float* __restrict__ out) {
    extern __shared__ unsigned sm[];
    unsigned* sQ = sm;                 // [256][68]
    unsigned* sK = sQ + 256 * 68;      // [64][68]
    unsigned* sV = sK + 64 * 68;       // [64][68]
    unsigned* sP = sV + 64 * 68;       // [256][68]

    const int t0 = blockIdx.x * 256;
    const int b  = blockIdx.y >> 4;
    const int hh = blockIdx.y & 15;

    const size_t base = (((size_t)b) * NH + hh) * (size_t)TT * DH;
    const size_t pl   = (size_t)BSZ * NH * TT * DH;
    const float* Qg = g_qkv + base;
    const float* Kg = g_qkv + pl + base;
    const float* Vg = g_qkv + 2 * pl + base;

    const int tid  = threadIdx.x;
    const int lane = tid & 31;
    const int wid  = tid >> 5;
    const int grp  = lane >> 2;
    const int tig  = lane & 3;
    const int rb   = wid * 32;

    // load Q tile once: 256x64 = 4096 uint4, 16 per thread (already tf32 bits)
    {
        const uint4* Qg4 = (const uint4*)(Qg + (size_t)t0 * DH);
#pragma unroll
        for (int i = 0; i < 16; i++) {
            int idx = i * 256 + tid;
            int r = idx >> 4, e4 = idx & 15;
            *(uint4*)&sQ[r * 68 + e4 * 4] = Qg4[idx];
        }
    }

    float o[2][8][4];
#pragma unroll
    for (int mt = 0; mt < 2; mt++)
#pragma unroll
        for (int nt = 0; nt < 8; nt++)
            o[mt][nt][0] = o[mt][nt][1] = o[mt][nt][2] = o[mt][nt][3] = 0.f;
    float mx[2][2] = {{-1e30f, -1e30f}, {-1e30f, -1e30f}};
    float li[2][2] = {{0.f, 0.f}, {0.f, 0.f}};

    for (int s0 = 0; s0 < TT; s0 += 64) {
        // load K,V tiles (64x64 each = 1024 uint4, 4/thread each)
        {
            const uint4* Kg4 = (const uint4*)(Kg + (size_t)s0 * DH);
            const uint4* Vg4 = (const uint4*)(Vg + (size_t)s0 * DH);
#pragma unroll
            for (int i = 0; i < 4; i++) {
                int idx = i * 256 + tid;
                int r = idx >> 4, e4 = idx & 15;
                *(uint4*)&sK[r * 68 + e4 * 4] = Kg4[idx];
                *(uint4*)&sV[r * 68 + e4 * 4] = Vg4[idx];
            }
        }
        __syncthreads();  // K,V visible (first iter: also covers Q load)

        // S = Q K^T  (32 rows x 64 s-cols per warp)
        float sa[2][8][4];
#pragma unroll
        for (int mt = 0; mt < 2; mt++)
#pragma unroll
            for (int nt = 0; nt < 8; nt++)
                sa[mt][nt][0] = sa[mt][nt][1] = sa[mt][nt][2] = sa[mt][nt][3] = 0.f;
#pragma unroll
        for (int ks = 0; ks < 8; ks++) {
            const int k0 = ks * 8;
            unsigned a[2][4];
#pragma unroll
            for (int mt = 0; mt < 2; mt++) {
                const int r = rb + mt * 16 + grp;
                a[mt][0] = sQ[r * 68 + k0 + tig];
                a[mt][1] = sQ[(r + 8) * 68 + k0 + tig];
                a[mt][2] = sQ[r * 68 + k0 + tig + 4];
                a[mt][3] = sQ[(r + 8) * 68 + k0 + tig + 4];
            }
#pragma unroll
            for (int nt = 0; nt < 8; nt++) {
                unsigned b0 = sK[(nt * 8 + grp) * 68 + k0 + tig];
                unsigned b1 = sK[(nt * 8 + grp) * 68 + k0 + tig + 4];
                mma8(sa[0][nt], a[0][0], a[0][1], a[0][2], a[0][3], b0, b1);
                mma8(sa[1][nt], a[1][0], a[1][1], a[1][2], a[1][3], b0, b1);
            }
        }

        // online softmax (scale 1/sqrt(64) = 0.125), per m-tile
#pragma unroll
        for (int mt = 0; mt < 2; mt++) {
            float txlo = -1e30f, txhi = -1e30f;
#pragma unroll
            for (int nt = 0; nt < 8; nt++) {
                sa[mt][nt][0] *= 0.125f; sa[mt][nt][1] *= 0.125f;
                sa[mt][nt][2] *= 0.125f; sa[mt][nt][3] *= 0.125f;
                txlo = fmaxf(txlo, fmaxf(sa[mt][nt][0], sa[mt][nt][1]));
                txhi = fmaxf(txhi, fmaxf(sa[mt][nt][2], sa[mt][nt][3]));
            }
            txlo = fmaxf(txlo, __shfl_xor_sync(~0u, txlo, 1));
            txlo = fmaxf(txlo, __shfl_xor_sync(~0u, txlo, 2));
            txhi = fmaxf(txhi, __shfl_xor_sync(~0u, txhi, 1));
            txhi = fmaxf(txhi, __shfl_xor_sync(~0u, txhi, 2));
            float nmlo = fmaxf(mx[mt][0], txlo), nmhi = fmaxf(mx[mt][1], txhi);
            float alo = __expf(mx[mt][0] - nmlo), ahi = __expf(mx[mt][1] - nmhi);
            mx[mt][0] = nmlo; mx[mt][1] = nmhi;

            float rslo = 0.f, rshi = 0.f;
#pragma unroll
            for (int nt = 0; nt < 8; nt++) {
                sa[mt][nt][0] = __expf(sa[mt][nt][0] - nmlo);
                sa[mt][nt][1] = __expf(sa[mt][nt][1] - nmlo);
                sa[mt][nt][2] = __expf(sa[mt][nt][2] - nmhi);
                sa[mt][nt][3] = __expf(sa[mt][nt][3] - nmhi);
                rslo += sa[mt][nt][0] + sa[mt][nt][1];
                rshi += sa[mt][nt][2] + sa[mt][nt][3];
            }
            rslo += __shfl_xor_sync(~0u, rslo, 1); rslo += __shfl_xor_sync(~0u, rslo, 2);
            rshi += __shfl_xor_sync(~0u, rshi, 1); rshi += __shfl_xor_sync(~0u, rshi, 2);
            li[mt][0] = li[mt][0] * alo + rslo;
            li[mt][1] = li[mt][1] * ahi + rshi;

            // rescale O, stash P raw bits (tf32-truncated by HW; own rows only)
#pragma unroll
            for (int nt = 0; nt < 8; nt++) {
                o[mt][nt][0] *= alo; o[mt][nt][1] *= alo;
                o[mt][nt][2] *= ahi; o[mt][nt][3] *= ahi;
                int sc = nt * 8 + 2 * tig;
                const int r = rb + mt * 16 + grp;
                *(uint2*)&sP[r * 68 + sc] =
                    make_uint2(__float_as_uint(sa[mt][nt][0]), __float_as_uint(sa[mt][nt][1]));
                *(uint2*)&sP[(r + 8) * 68 + sc] =
                    make_uint2(__float_as_uint(sa[mt][nt][2]), __float_as_uint(sa[mt][nt][3]));
            }
        }
        __syncwarp();

        // O += P V
#pragma unroll
        for (int ks = 0; ks < 8; ks++) {
            const int k0 = ks * 8;
            unsigned a[2][4];
#pragma unroll
            for (int mt = 0; mt < 2; mt++) {
                const int r = rb + mt * 16 + grp;
                a[mt][0] = sP[r * 68 + k0 + tig];
                a[mt][1] = sP[(r + 8) * 68 + k0 + tig];
                a[mt][2] = sP[r * 68 + k0 + tig + 4];
                a[mt][3] = sP[(r + 8) * 68 + k0 + tig + 4];
            }
#pragma unroll
            for (int nt = 0; nt < 8; nt++) {
                unsigned b0 = sV[(k0 + tig) * 68 + nt * 8 + grp];
                unsigned b1 = sV[(k0 + tig + 4) * 68 + nt * 8 + grp];
                mma8(o[0][nt], a[0][0], a[0][1], a[0][2], a[0][3], b0, b1);
                mma8(o[1][nt], a[1][0], a[1][1], a[1][2], a[1][3], b0, b1);
            }
        }
        __syncthreads();  // all warps done with sK/sV before next overwrite
    }

    // epilogue: divide by l, write transposed out[b, h*64+e, t]
    float* ob = out + ((size_t)b * DD + hh * DH) * TT;
#pragma unroll
    for (int mt = 0; mt < 2; mt++) {
        float ilo = 1.f / li[mt][0], ihi = 1.f / li[mt][1];
        const int rlo = t0 + rb + mt * 16 + grp;
        const int rhi = rlo + 8;
#pragma unroll
        for (int nt = 0; nt < 8; nt++) {
            int e = nt * 8 + 2 * tig;
            ob[(size_t)e * TT + rlo]       = o[mt][nt][0] * ilo;
            ob[(size_t)(e + 1) * TT + rlo] = o[mt][nt][1] * ilo;
            ob[(size_t)e * TT + rhi]       = o[mt][nt][2] * ihi;
            ob[(size_t)(e + 1) * TT + rhi] = o[mt][nt][3] * ihi;
        }
    }
}

extern "C" void kernel_launch(void* const* d_in, const int* in_sizes, int n_in,
                              void* d_out, int out_size) {
    (void)in_sizes; (void)n_in; (void)out_size;
    const float* x   = (const float*)d_in[0];   // [4,1024,2048] fp32
    const float* qkv = (const float*)d_in[1];   // [3,16,1024,64] fp32
    float* out = (float*)d_out;                 // [4,1024,2048] fp32

    qkv_proj_kernel<<<dim3(TT / 256, 3 * BSZ * NH), 256>>>(x, qkv);

    const int smem2 = SMEM2_WORDS * 4;  // 174080 B
    cudaFuncSetAttribute(attn_kernel, cudaFuncAttributeMaxDynamicSharedMemorySize, smem2);
    attn_kernel<<<dim3(TT / 256, BSZ * NH), 256, smem2>>>(out);
}